// round 7
// baseline (speedup 1.0000x reference)
#include <cuda_runtime.h>
#include <cstdint>

// ---- Problem constants -----------------------------------------------------
#define BB 16
#define NN 8192
#define NIN 4096
#define BN (BB * NN)          // 131072
#define KTOT (NN + NIN)       // 12288 virtual rows (W_int then W_ext)
#define NSPLIT 24
#define TILES 16              // 512 cols per tile

#define ALPHA_F 0.9512294245007140f
#define ONE_MINUS_ALPHA_F (1.0f - 0.9512294245007140f)
#define RHO_A_F 0.9950124791926823f
#define BETA_F 1.8f
#define TH0_F 1.0f

// ---- Device scratch (static globals, allowed) ------------------------------
__device__ unsigned g_umask[KTOT];           // 16-bit batch mask per row
__device__ unsigned g_ulist[KTOT];           // packed (mask<<16)|k, compacted
__device__ int      g_ucnt;
__device__ float    g_partial[NSPLIT * BB * NN];   // 12.6 MB split-K partials

// ---- Kernel 1: per-row 16-bit batch activity mask --------------------------
// grid 24 x 512 = 12288 threads, one row each; 16 coalesced loads per thread.
// Blocks 0..15 are internal rows, 16..23 external (8192 = 16*512 boundary).
__global__ __launch_bounds__(512)
void k_mask(const float* __restrict__ Xd, const float* __restrict__ Xext) {
    int k = blockIdx.x * 512 + threadIdx.x;
    unsigned m = 0;
    if (k < NN) {
#pragma unroll
        for (int b = 0; b < 16; b++)
            m |= (Xd[(size_t)(7 * BB + b) * NN + k] > 0.5f ? 1u : 0u) << b;
    } else {
#pragma unroll
        for (int b = 0; b < 16; b++)
            m |= (Xext[(size_t)b * NIN + (k - NN)] > 0.5f ? 1u : 0u) << b;
    }
    g_umask[k] = m;
}

// ---- Kernel 2: single-block deterministic compaction -----------------------
__global__ __launch_bounds__(1024)
void k_compact() {
    __shared__ int s_w[32];
    __shared__ int s_tot;
    __shared__ int s_carry;
    int tid = threadIdx.x, w = tid >> 5, lane = tid & 31;
    if (tid == 0) s_carry = 0;
    __syncthreads();
    unsigned lt = (1u << lane) - 1u;

    for (int r = 0; r < KTOT / 1024; r++) {
        int k = r * 1024 + tid;
        unsigned m = g_umask[k];
        unsigned bal = __ballot_sync(0xffffffffu, m != 0);
        if (lane == 0) s_w[w] = __popc(bal);
        __syncthreads();
        if (w == 0) {
            int v = s_w[lane];
            int incl = v;
#pragma unroll
            for (int d = 1; d < 32; d <<= 1) {
                int o = __shfl_up_sync(0xffffffffu, incl, d);
                if (lane >= d) incl += o;
            }
            s_w[lane] = incl - v;
            if (lane == 31) s_tot = incl;
        }
        __syncthreads();
        if (m)
            g_ulist[s_carry + s_w[w] + __popc(bal & lt)] = (m << 16) | (unsigned)k;
        __syncthreads();
        if (tid == 0) s_carry += s_tot;
        __syncthreads();
    }
    if (tid == 0) g_ucnt = s_carry;
}

// ---- Kernel 3: union-row sparse sum, 16 register accumulators --------------
// grid (TILES=16, NSPLIT=24) x 128 threads. Warp covers 512 B/row (float4).
// Each weight row segment read ONCE; ffs+switch adds into active batches only.
#define ACC4(A) { A.x += w.x; A.y += w.y; A.z += w.z; A.w += w.w; }

__global__ __launch_bounds__(128)
void spmm_union(const float* __restrict__ Wint,
                const float* __restrict__ Wext) {
    const int tile = blockIdx.x;
    const int s    = blockIdx.y;
    const int tid  = threadIdx.x;
    const int col  = tile * 512 + tid * 4;

    float4 a0 = {0,0,0,0}, a1 = {0,0,0,0}, a2 = {0,0,0,0}, a3 = {0,0,0,0};
    float4 a4 = {0,0,0,0}, a5 = {0,0,0,0}, a6 = {0,0,0,0}, a7 = {0,0,0,0};
    float4 a8 = {0,0,0,0}, a9 = {0,0,0,0}, a10 = {0,0,0,0}, a11 = {0,0,0,0};
    float4 a12 = {0,0,0,0}, a13 = {0,0,0,0}, a14 = {0,0,0,0}, a15 = {0,0,0,0};

    int cnt = g_ucnt;
    int seg = (cnt + NSPLIT - 1) / NSPLIT;
    int start = s * seg;
    int end = start + seg; if (end > cnt) end = cnt;
    int len = end - start; if (len < 0) len = 0;
    const unsigned* __restrict__ ul = g_ulist + start;

    int i = 0;
    for (; i + 8 <= len; i += 8) {
        unsigned pk[8];
#pragma unroll
        for (int u = 0; u < 8; u++) pk[u] = __ldg(&ul[i + u]);
        float4 wv[8];
#pragma unroll
        for (int u = 0; u < 8; u++) {
            unsigned k = pk[u] & 0xFFFFu;
            const float* p = (k < NN) ? (Wint + ((size_t)k << 13))
                                      : (Wext + ((size_t)(k - NN) << 13));
            wv[u] = *(const float4*)(p + col);
        }
#pragma unroll
        for (int u = 0; u < 8; u++) {
            unsigned m = pk[u] >> 16;
            float4 w = wv[u];
            while (m) {
                int b = __ffs(m) - 1;
                m &= m - 1;
                switch (b) {
                    case 0:  ACC4(a0);  break;
                    case 1:  ACC4(a1);  break;
                    case 2:  ACC4(a2);  break;
                    case 3:  ACC4(a3);  break;
                    case 4:  ACC4(a4);  break;
                    case 5:  ACC4(a5);  break;
                    case 6:  ACC4(a6);  break;
                    case 7:  ACC4(a7);  break;
                    case 8:  ACC4(a8);  break;
                    case 9:  ACC4(a9);  break;
                    case 10: ACC4(a10); break;
                    case 11: ACC4(a11); break;
                    case 12: ACC4(a12); break;
                    case 13: ACC4(a13); break;
                    case 14: ACC4(a14); break;
                    default: ACC4(a15); break;
                }
            }
        }
    }
    for (; i < len; i++) {
        unsigned pkx = __ldg(&ul[i]);
        unsigned k = pkx & 0xFFFFu;
        const float* p = (k < NN) ? (Wint + ((size_t)k << 13))
                                  : (Wext + ((size_t)(k - NN) << 13));
        float4 w = *(const float4*)(p + col);
        unsigned m = pkx >> 16;
        while (m) {
            int b = __ffs(m) - 1;
            m &= m - 1;
            switch (b) {
                case 0:  ACC4(a0);  break;
                case 1:  ACC4(a1);  break;
                case 2:  ACC4(a2);  break;
                case 3:  ACC4(a3);  break;
                case 4:  ACC4(a4);  break;
                case 5:  ACC4(a5);  break;
                case 6:  ACC4(a6);  break;
                case 7:  ACC4(a7);  break;
                case 8:  ACC4(a8);  break;
                case 9:  ACC4(a9);  break;
                case 10: ACC4(a10); break;
                case 11: ACC4(a11); break;
                case 12: ACC4(a12); break;
                case 13: ACC4(a13); break;
                case 14: ACC4(a14); break;
                default: ACC4(a15); break;
            }
        }
    }

    // Write split-K partials: [s][b][8192] layout
    float* pb = g_partial + (((size_t)s * BB) << 13) + col;
#define STP(b, A) *(float4*)(pb + ((size_t)(b) << 13)) = A;
    STP(0, a0)  STP(1, a1)  STP(2, a2)   STP(3, a3)
    STP(4, a4)  STP(5, a5)  STP(6, a6)   STP(7, a7)
    STP(8, a8)  STP(9, a9)  STP(10, a10) STP(11, a11)
    STP(12, a12) STP(13, a13) STP(14, a14) STP(15, a15)
#undef STP
}

// ---- Kernel 4: merged prep + split-K reduce + membrane epilogue ------------
// out layout: X [0,BN) | V_new [BN,2BN) | a_new [2BN,3BN) | Xd_new [3BN,11BN)
__global__ __launch_bounds__(256)
void k_final(const float4* __restrict__ V4,
             const float4* __restrict__ a4v,
             const float4* __restrict__ Xd4,
             float4* __restrict__ out4) {
    int i = blockIdx.x * blockDim.x + threadIdx.x;
    const int BN4 = BN / 4;
    if (i < BN4) {
        float4 Vv = V4[i];
        float4 av = a4v[i];

        // reduce 24 split partials
        float4 cur = {0, 0, 0, 0};
#pragma unroll
        for (int s = 0; s < NSPLIT; s++) {
            float4 p = *(const float4*)(&g_partial[(size_t)s * BN + (size_t)i * 4]);
            cur.x += p.x; cur.y += p.y; cur.z += p.z; cur.w += p.w;
        }

        float4 x, an, vn;
        x.x = (Vv.x >= TH0_F + BETA_F * av.x) ? 1.0f : 0.0f;
        x.y = (Vv.y >= TH0_F + BETA_F * av.y) ? 1.0f : 0.0f;
        x.z = (Vv.z >= TH0_F + BETA_F * av.z) ? 1.0f : 0.0f;
        x.w = (Vv.w >= TH0_F + BETA_F * av.w) ? 1.0f : 0.0f;
        an.x = RHO_A_F * av.x + x.x;
        an.y = RHO_A_F * av.y + x.y;
        an.z = RHO_A_F * av.z + x.z;
        an.w = RHO_A_F * av.w + x.w;
        vn.x = ALPHA_F * Vv.x * (1.0f - x.x) + ONE_MINUS_ALPHA_F * cur.x;
        vn.y = ALPHA_F * Vv.y * (1.0f - x.y) + ONE_MINUS_ALPHA_F * cur.y;
        vn.z = ALPHA_F * Vv.z * (1.0f - x.z) + ONE_MINUS_ALPHA_F * cur.z;
        vn.w = ALPHA_F * Vv.w * (1.0f - x.w) + ONE_MINUS_ALPHA_F * cur.w;

        out4[i] = x;               // X
        out4[BN4 + i] = vn;        // V_new
        out4[2 * BN4 + i] = an;    // a_new
        out4[3 * BN4 + i] = x;     // Xd_new slot 0
    }
    if (i < 7 * BN4) {
        out4[4 * BN4 + i] = Xd4[i];  // Xd_new slots 1..7 = old slots 0..6
    }
}

// ---- Launch ----------------------------------------------------------------
extern "C" void kernel_launch(void* const* d_in, const int* in_sizes, int n_in,
                              void* d_out, int out_size) {
    const float* V    = (const float*)d_in[0];
    const float* a    = (const float*)d_in[1];
    const float* Xd   = (const float*)d_in[2];
    const float* Xext = (const float*)d_in[3];
    const float* Wint = (const float*)d_in[4];
    const float* Wext = (const float*)d_in[5];
    float* out = (float*)d_out;

    k_mask<<<KTOT / 512, 512>>>(Xd, Xext);
    k_compact<<<1, 1024>>>();

    dim3 grid(TILES, NSPLIT);
    spmm_union<<<grid, 128>>>(Wint, Wext);

    int total4 = 7 * BN / 4;
    k_final<<<(total4 + 255) / 256, 256>>>(
        (const float4*)V, (const float4*)a, (const float4*)Xd, (float4*)out);
}

// round 9
// speedup vs baseline: 1.1596x; 1.1596x over previous
#include <cuda_runtime.h>
#include <cstdint>

// ---- Problem constants -----------------------------------------------------
#define BB 16
#define NN 8192
#define NIN 4096
#define BN (BB * NN)          // 131072
#define KTOT (NN + NIN)       // 12288 virtual rows (W_int then W_ext)
#define NSPLIT 16
#define TILES 16              // 512 cols per tile

#define ALPHA_F 0.9512294245007140f
#define ONE_MINUS_ALPHA_F (1.0f - 0.9512294245007140f)
#define RHO_A_F 0.9950124791926823f
#define BETA_F 1.8f
#define TH0_F 1.0f

// ---- Device scratch (static globals, allowed) ------------------------------
__device__ unsigned g_umask[KTOT];                  // 16-bit batch mask per row
__device__ unsigned g_ulist[KTOT];                  // packed (mask<<16)|k
__device__ int      g_ucnt;
__device__ float    g_partial[NSPLIT * BB * NN];    // 8.4 MB split-K partials

// ---- Kernel 1: per-row 16-bit batch activity mask --------------------------
__global__ __launch_bounds__(512)
void k_mask(const float* __restrict__ Xd, const float* __restrict__ Xext) {
    int k = blockIdx.x * 512 + threadIdx.x;
    unsigned m = 0;
    if (k < NN) {
#pragma unroll
        for (int b = 0; b < 16; b++)
            m |= (Xd[(size_t)(7 * BB + b) * NN + k] > 0.5f ? 1u : 0u) << b;
    } else {
#pragma unroll
        for (int b = 0; b < 16; b++)
            m |= (Xext[(size_t)b * NIN + (k - NN)] > 0.5f ? 1u : 0u) << b;
    }
    g_umask[k] = m;
}

// ---- Kernel 2: single-block deterministic compaction -----------------------
__global__ __launch_bounds__(1024)
void k_compact() {
    __shared__ int s_w[32];
    __shared__ int s_tot;
    __shared__ int s_carry;
    int tid = threadIdx.x, w = tid >> 5, lane = tid & 31;
    if (tid == 0) s_carry = 0;
    __syncthreads();
    unsigned lt = (1u << lane) - 1u;

    for (int r = 0; r < KTOT / 1024; r++) {
        int k = r * 1024 + tid;
        unsigned m = g_umask[k];
        unsigned bal = __ballot_sync(0xffffffffu, m != 0);
        if (lane == 0) s_w[w] = __popc(bal);
        __syncthreads();
        if (w == 0) {
            int v = s_w[lane];
            int incl = v;
#pragma unroll
            for (int d = 1; d < 32; d <<= 1) {
                int o = __shfl_up_sync(0xffffffffu, incl, d);
                if (lane >= d) incl += o;
            }
            s_w[lane] = incl - v;
            if (lane == 31) s_tot = incl;
        }
        __syncthreads();
        if (m)
            g_ulist[s_carry + s_w[w] + __popc(bal & lt)] = (m << 16) | (unsigned)k;
        __syncthreads();
        if (tid == 0) s_carry += s_tot;
        __syncthreads();
    }
    if (tid == 0) g_ucnt = s_carry;
}

// ---- Kernel 3: union-row sparse sum, SMEM-indexed batch accumulators -------
// grid (TILES=16, NSPLIT=16) x 128 threads. Each weight-row segment is read
// from gmem ONCE; contributions dispatched into s_acc[b][tid] (tight ffs loop,
// no register-array spills, no __syncthreads in the main loop since each
// thread owns its own 16 slots).
__global__ __launch_bounds__(128)
void spmm_union(const float* __restrict__ Wint,
                const float* __restrict__ Wext) {
    __shared__ float4 s_acc[BB][128];     // 32 KB, conflict-free (16B stride)

    const int tile = blockIdx.x;
    const int s    = blockIdx.y;
    const int tid  = threadIdx.x;
    const int col  = tile * 512 + tid * 4;

#pragma unroll
    for (int b = 0; b < BB; b++) s_acc[b][tid] = make_float4(0.f, 0.f, 0.f, 0.f);

    int cnt = g_ucnt;
    int seg = (cnt + NSPLIT - 1) / NSPLIT;
    int start = s * seg;
    int end = start + seg; if (end > cnt) end = cnt;
    int len = end - start; if (len < 0) len = 0;
    const unsigned* __restrict__ ul = g_ulist + start;

    int i = 0;
    for (; i + 12 <= len; i += 12) {
        unsigned pk[12];
#pragma unroll
        for (int u = 0; u < 12; u++) pk[u] = __ldg(&ul[i + u]);
        float4 wv[12];
#pragma unroll
        for (int u = 0; u < 12; u++) {
            unsigned k = pk[u] & 0xFFFFu;
            const float* p = (k < NN) ? (Wint + ((size_t)k << 13))
                                      : (Wext + ((size_t)(k - NN) << 13));
            wv[u] = *(const float4*)(p + col);
        }
#pragma unroll
        for (int u = 0; u < 12; u++) {
            unsigned m = pk[u] >> 16;
            float4 w = wv[u];
            while (m) {
                int b = __ffs(m) - 1;
                m &= m - 1;
                float4 t = s_acc[b][tid];
                t.x += w.x; t.y += w.y; t.z += w.z; t.w += w.w;
                s_acc[b][tid] = t;
            }
        }
    }
    for (; i < len; i++) {
        unsigned pkx = __ldg(&ul[i]);
        unsigned k = pkx & 0xFFFFu;
        const float* p = (k < NN) ? (Wint + ((size_t)k << 13))
                                  : (Wext + ((size_t)(k - NN) << 13));
        float4 w = *(const float4*)(p + col);
        unsigned m = pkx >> 16;
        while (m) {
            int b = __ffs(m) - 1;
            m &= m - 1;
            float4 t = s_acc[b][tid];
            t.x += w.x; t.y += w.y; t.z += w.z; t.w += w.w;
            s_acc[b][tid] = t;
        }
    }

    // Flush accumulators to split-K partials: layout [s][b][8192]
    float* pb = g_partial + (((size_t)s * BB) << 13) + col;
#pragma unroll
    for (int b = 0; b < BB; b++)
        *(float4*)(pb + ((size_t)b << 13)) = s_acc[b][tid];
}

// ---- Kernel 4: merged prep + split-K reduce + membrane epilogue ------------
// out layout: X [0,BN) | V_new [BN,2BN) | a_new [2BN,3BN) | Xd_new [3BN,11BN)
__global__ __launch_bounds__(256)
void k_final(const float4* __restrict__ V4,
             const float4* __restrict__ a4v,
             const float4* __restrict__ Xd4,
             float4* __restrict__ out4) {
    int i = blockIdx.x * blockDim.x + threadIdx.x;
    const int BN4 = BN / 4;
    if (i < BN4) {
        float4 Vv = V4[i];
        float4 av = a4v[i];

        float4 cur = make_float4(0.f, 0.f, 0.f, 0.f);
#pragma unroll
        for (int s = 0; s < NSPLIT; s++) {
            float4 p = *(const float4*)(&g_partial[(size_t)s * BN + (size_t)i * 4]);
            cur.x += p.x; cur.y += p.y; cur.z += p.z; cur.w += p.w;
        }

        float4 x, an, vn;
        x.x = (Vv.x >= TH0_F + BETA_F * av.x) ? 1.0f : 0.0f;
        x.y = (Vv.y >= TH0_F + BETA_F * av.y) ? 1.0f : 0.0f;
        x.z = (Vv.z >= TH0_F + BETA_F * av.z) ? 1.0f : 0.0f;
        x.w = (Vv.w >= TH0_F + BETA_F * av.w) ? 1.0f : 0.0f;
        an.x = RHO_A_F * av.x + x.x;
        an.y = RHO_A_F * av.y + x.y;
        an.z = RHO_A_F * av.z + x.z;
        an.w = RHO_A_F * av.w + x.w;
        vn.x = ALPHA_F * Vv.x * (1.0f - x.x) + ONE_MINUS_ALPHA_F * cur.x;
        vn.y = ALPHA_F * Vv.y * (1.0f - x.y) + ONE_MINUS_ALPHA_F * cur.y;
        vn.z = ALPHA_F * Vv.z * (1.0f - x.z) + ONE_MINUS_ALPHA_F * cur.z;
        vn.w = ALPHA_F * Vv.w * (1.0f - x.w) + ONE_MINUS_ALPHA_F * cur.w;

        out4[i] = x;               // X
        out4[BN4 + i] = vn;        // V_new
        out4[2 * BN4 + i] = an;    // a_new
        out4[3 * BN4 + i] = x;     // Xd_new slot 0
    }
    if (i < 7 * BN4) {
        out4[4 * BN4 + i] = Xd4[i];  // Xd_new slots 1..7 = old slots 0..6
    }
}

// ---- Launch ----------------------------------------------------------------
extern "C" void kernel_launch(void* const* d_in, const int* in_sizes, int n_in,
                              void* d_out, int out_size) {
    const float* V    = (const float*)d_in[0];
    const float* a    = (const float*)d_in[1];
    const float* Xd   = (const float*)d_in[2];
    const float* Xext = (const float*)d_in[3];
    const float* Wint = (const float*)d_in[4];
    const float* Wext = (const float*)d_in[5];
    float* out = (float*)d_out;

    k_mask<<<KTOT / 512, 512>>>(Xd, Xext);
    k_compact<<<1, 1024>>>();

    dim3 grid(TILES, NSPLIT);
    spmm_union<<<grid, 128>>>(Wint, Wext);

    int total4 = 7 * BN / 4;
    k_final<<<(total4 + 255) / 256, 256>>>(
        (const float4*)V, (const float4*)a, (const float4*)Xd, (float4*)out);
}

// round 10
// speedup vs baseline: 1.7084x; 1.4732x over previous
#include <cuda_runtime.h>
#include <cstdint>

// ---- Problem constants -----------------------------------------------------
#define BB 16
#define NN 8192
#define NIN 4096
#define BN (BB * NN)          // 131072
#define KTOT (NN + NIN)       // 12288 virtual rows (W_int then W_ext)
#define NSPLIT 12
#define TILE_COLS 256
#define NTILES (NN / TILE_COLS)   // 32
#define CHUNK 16
#define SEG_MAX 1024          // >= ceil(KTOT/NSPLIT)

#define ALPHA_F 0.9512294245007140f
#define ONE_MINUS_ALPHA_F (1.0f - 0.9512294245007140f)
#define RHO_A_F 0.9950124791926823f
#define BETA_F 1.8f
#define TH0_F 1.0f

// ---- Device scratch (static globals, allowed) ------------------------------
__device__ unsigned g_umask[KTOT];                  // 16-bit batch mask per row
__device__ unsigned g_ulist[KTOT];                  // packed (mask<<16)|row
__device__ int      g_ucnt;
__device__ float    g_partial[NSPLIT * BB * NN];    // 6.3 MB split-K partials

// ---- cp.async helpers -------------------------------------------------------
#define CP_ASYNC16(dst_smem, src_gmem) \
    asm volatile("cp.async.cg.shared.global [%0], [%1], 16;" \
                 :: "r"(dst_smem), "l"(src_gmem) : "memory")
#define CP_COMMIT() asm volatile("cp.async.commit_group;" ::: "memory")
#define CP_WAIT1()  asm volatile("cp.async.wait_group 1;" ::: "memory")

// ---- Kernel 1: per-row 16-bit batch activity mask --------------------------
__global__ __launch_bounds__(512)
void k_mask(const float* __restrict__ Xd, const float* __restrict__ Xext) {
    int k = blockIdx.x * 512 + threadIdx.x;
    unsigned m = 0;
    if (k < NN) {
#pragma unroll
        for (int b = 0; b < 16; b++)
            m |= (Xd[(size_t)(7 * BB + b) * NN + k] > 0.5f ? 1u : 0u) << b;
    } else {
#pragma unroll
        for (int b = 0; b < 16; b++)
            m |= (Xext[(size_t)b * NIN + (k - NN)] > 0.5f ? 1u : 0u) << b;
    }
    g_umask[k] = m;
}

// ---- Kernel 2: single-block deterministic compaction -----------------------
__global__ __launch_bounds__(1024)
void k_compact() {
    __shared__ int s_w[32];
    __shared__ int s_tot;
    __shared__ int s_carry;
    int tid = threadIdx.x, w = tid >> 5, lane = tid & 31;
    if (tid == 0) s_carry = 0;
    __syncthreads();
    unsigned lt = (1u << lane) - 1u;

    for (int r = 0; r < KTOT / 1024; r++) {
        int k = r * 1024 + tid;
        unsigned m = g_umask[k];
        unsigned bal = __ballot_sync(0xffffffffu, m != 0);
        if (lane == 0) s_w[w] = __popc(bal);
        __syncthreads();
        if (w == 0) {
            int v = s_w[lane];
            int incl = v;
#pragma unroll
            for (int d = 1; d < 32; d <<= 1) {
                int o = __shfl_up_sync(0xffffffffu, incl, d);
                if (lane >= d) incl += o;
            }
            s_w[lane] = incl - v;
            if (lane == 31) s_tot = incl;
        }
        __syncthreads();
        if (m)
            g_ulist[s_carry + s_w[w] + __popc(bal & lt)] = (m << 16) | (unsigned)k;
        __syncthreads();
        if (tid == 0) s_carry += s_tot;
        __syncthreads();
    }
    if (tid == 0) g_ucnt = s_carry;
}

// ---- Kernel 3: union-row sparse sum, producer/consumer in one CTA ----------
// grid (NTILES=32, NSPLIT=12) x 256 threads (8 warps).
// cp.async stages CHUNK=16 row segments (16 x 1KB) double-buffered in smem;
// warp w accumulates batches {2w, 2w+1} in registers (static indices).
__global__ __launch_bounds__(256)
void spmm_union(const float* __restrict__ Wint,
                const float* __restrict__ Wext) {
    __shared__ unsigned s_ent[SEG_MAX];             // 4 KB entries
    __shared__ float4   s_row[2][CHUNK][TILE_COLS / 4];  // 2 x 16 KB rows

    const int tile = blockIdx.x;
    const int s    = blockIdx.y;
    const int tid  = threadIdx.x;
    const int w    = tid >> 5;
    const int lane = tid & 31;

    int cnt = g_ucnt;
    int seg = (cnt + NSPLIT - 1) / NSPLIT;
    int start = s * seg;
    int end = start + seg; if (end > cnt) end = cnt;
    int len = end - start; if (len < 0) len = 0;

    // Stage the entry list segment into smem once.
    for (int i = tid; i < len; i += 256) s_ent[i] = g_ulist[start + i];
    __syncthreads();

    const unsigned bit0 = 1u << (2 * w);
    const unsigned bit1 = 2u << (2 * w);
    float4 a00 = {0,0,0,0}, a01 = {0,0,0,0};   // batch 2w,   2 float4 (8 cols)
    float4 a10 = {0,0,0,0}, a11 = {0,0,0,0};   // batch 2w+1

    const int nchunk = (len + CHUNK - 1) / CHUNK;
    const int e_of_t = tid >> 4;     // 16 threads per row
    const int sub    = tid & 15;     // 16B slot group within row

    // Issue cp.async loads for chunk c into buffer buf.
    auto issue = [&](int c, int buf) {
        int base = c * CHUNK;
        int gi = base + e_of_t;
        if (gi >= len) gi = len - 1;             // clamp (harmless dup load)
        unsigned ent = s_ent[gi];
        unsigned k = ent & 0xFFFFu;
        const float* src = ((k < NN) ? (Wint + ((size_t)k << 13))
                                     : (Wext + ((size_t)(k - NN) << 13)))
                           + tile * TILE_COLS;
#pragma unroll
        for (int j = 0; j < 4; j++) {
            int slot = sub + j * 16;             // 16B slot within 1KB row
            unsigned dst = (unsigned)__cvta_generic_to_shared(
                &s_row[buf][e_of_t][slot]);
            CP_ASYNC16(dst, src + slot * 4);
        }
    };

    if (nchunk > 0) {
        issue(0, 0);
        CP_COMMIT();
        for (int c = 0; c < nchunk; c++) {
            int buf = c & 1;
            if (c + 1 < nchunk) issue(c + 1, buf ^ 1);
            CP_COMMIT();                          // one group per iteration
            CP_WAIT1();                           // chunk c resident
            __syncthreads();

            int base = c * CHUNK;
            int lim = len - base; if (lim > CHUNK) lim = CHUNK;
            for (int i = 0; i < lim; i++) {
                unsigned ent = s_ent[base + i];   // warp-uniform
                unsigned m = ent >> 16;
                if (m & (bit0 | bit1)) {
                    float4 v0 = s_row[buf][i][lane * 2];
                    float4 v1 = s_row[buf][i][lane * 2 + 1];
                    if (m & bit0) {
                        a00.x += v0.x; a00.y += v0.y; a00.z += v0.z; a00.w += v0.w;
                        a01.x += v1.x; a01.y += v1.y; a01.z += v1.z; a01.w += v1.w;
                    }
                    if (m & bit1) {
                        a10.x += v0.x; a10.y += v0.y; a10.z += v0.z; a10.w += v0.w;
                        a11.x += v1.x; a11.y += v1.y; a11.z += v1.z; a11.w += v1.w;
                    }
                }
            }
            __syncthreads();                      // protect buf before reuse
        }
    }

    // Write partials: layout [s][b][8192]; warp w owns batches 2w, 2w+1.
    int colb = tile * TILE_COLS + lane * 8;
    float* p0 = g_partial + (((size_t)s * BB + 2 * w) << 13) + colb;
    float* p1 = g_partial + (((size_t)s * BB + 2 * w + 1) << 13) + colb;
    *(float4*)(p0)     = a00;
    *(float4*)(p0 + 4) = a01;
    *(float4*)(p1)     = a10;
    *(float4*)(p1 + 4) = a11;
}

// ---- Kernel 4: merged prep + split-K reduce + membrane epilogue ------------
// out layout: X [0,BN) | V_new [BN,2BN) | a_new [2BN,3BN) | Xd_new [3BN,11BN)
__global__ __launch_bounds__(256)
void k_final(const float4* __restrict__ V4,
             const float4* __restrict__ a4v,
             const float4* __restrict__ Xd4,
             float4* __restrict__ out4) {
    int i = blockIdx.x * blockDim.x + threadIdx.x;
    const int BN4 = BN / 4;
    if (i < BN4) {
        float4 Vv = V4[i];
        float4 av = a4v[i];

        float4 cur = make_float4(0.f, 0.f, 0.f, 0.f);
#pragma unroll
        for (int s = 0; s < NSPLIT; s++) {
            float4 p = *(const float4*)(&g_partial[(size_t)s * BN + (size_t)i * 4]);
            cur.x += p.x; cur.y += p.y; cur.z += p.z; cur.w += p.w;
        }

        float4 x, an, vn;
        x.x = (Vv.x >= TH0_F + BETA_F * av.x) ? 1.0f : 0.0f;
        x.y = (Vv.y >= TH0_F + BETA_F * av.y) ? 1.0f : 0.0f;
        x.z = (Vv.z >= TH0_F + BETA_F * av.z) ? 1.0f : 0.0f;
        x.w = (Vv.w >= TH0_F + BETA_F * av.w) ? 1.0f : 0.0f;
        an.x = RHO_A_F * av.x + x.x;
        an.y = RHO_A_F * av.y + x.y;
        an.z = RHO_A_F * av.z + x.z;
        an.w = RHO_A_F * av.w + x.w;
        vn.x = ALPHA_F * Vv.x * (1.0f - x.x) + ONE_MINUS_ALPHA_F * cur.x;
        vn.y = ALPHA_F * Vv.y * (1.0f - x.y) + ONE_MINUS_ALPHA_F * cur.y;
        vn.z = ALPHA_F * Vv.z * (1.0f - x.z) + ONE_MINUS_ALPHA_F * cur.z;
        vn.w = ALPHA_F * Vv.w * (1.0f - x.w) + ONE_MINUS_ALPHA_F * cur.w;

        out4[i] = x;               // X
        out4[BN4 + i] = vn;        // V_new
        out4[2 * BN4 + i] = an;    // a_new
        out4[3 * BN4 + i] = x;     // Xd_new slot 0
    }
    if (i < 7 * BN4) {
        out4[4 * BN4 + i] = Xd4[i];  // Xd_new slots 1..7 = old slots 0..6
    }
}

// ---- Launch ----------------------------------------------------------------
extern "C" void kernel_launch(void* const* d_in, const int* in_sizes, int n_in,
                              void* d_out, int out_size) {
    const float* V    = (const float*)d_in[0];
    const float* a    = (const float*)d_in[1];
    const float* Xd   = (const float*)d_in[2];
    const float* Xext = (const float*)d_in[3];
    const float* Wint = (const float*)d_in[4];
    const float* Wext = (const float*)d_in[5];
    float* out = (float*)d_out;

    k_mask<<<KTOT / 512, 512>>>(Xd, Xext);
    k_compact<<<1, 1024>>>();

    dim3 grid(NTILES, NSPLIT);
    spmm_union<<<grid, 256>>>(Wint, Wext);

    int total4 = 7 * BN / 4;
    k_final<<<(total4 + 255) / 256, 256>>>(
        (const float4*)V, (const float4*)a, (const float4*)Xd, (float4*)out);
}